// round 1
// baseline (speedup 1.0000x reference)
#include <cuda_runtime.h>

// ExponentialMovingAverage: out[b,t,f] = w*x[b,t,f] + (1-w)*out[b,t-1,f],
// out[b,-1,f] = initial_state[b,f], w = clip(smooth[0], 0, 1).
// Exact chunked parallel scan (3 phases), fully HBM-bound.

namespace {
constexpr int B  = 16;
constexpr int T  = 8192;
constexpr int F  = 512;
constexpr int NC = 64;        // chunks along T
constexpr int L  = T / NC;    // 128 steps per chunk
constexpr int F4 = F / 4;     // 128 float4 lanes per (b,t) row
}

// Scratch (static device allocation — no runtime allocs).
__device__ float4 g_s [B * NC * F4];   // chunk-local zero-init scan endpoints
__device__ float4 g_a0[B * NC * F4];   // true start state of each chunk

__device__ __forceinline__ float load_w(const float* __restrict__ smooth) {
    return fminf(fmaxf(smooth[0], 0.0f), 1.0f);
}

// Phase 1: per (b, chunk) block, compute s_c = local scan with zero init.
__global__ void __launch_bounds__(F4) ema_phase1(const float* __restrict__ x,
                                                 const float* __restrict__ smooth) {
    const int c  = blockIdx.x;
    const int b  = blockIdx.y;
    const int f4 = threadIdx.x;
    const float w = load_w(smooth);
    const float d = 1.0f - w;

    const float4* xp = reinterpret_cast<const float4*>(x)
                     + (size_t)b * T * F4 + (size_t)c * L * F4 + f4;

    float ax = 0.f, ay = 0.f, az = 0.f, aw_ = 0.f;
    #pragma unroll 8
    for (int j = 0; j < L; ++j) {
        const float4 v = __ldg(xp + (size_t)j * F4);
        ax  = fmaf(d, ax,  w * v.x);
        ay  = fmaf(d, ay,  w * v.y);
        az  = fmaf(d, az,  w * v.z);
        aw_ = fmaf(d, aw_, w * v.w);
    }
    g_s[((size_t)b * NC + c) * F4 + f4] = make_float4(ax, ay, az, aw_);
}

// Phase 2: sequential combine across the NC chunks per sequence (tiny).
// a_start[c] known; a_start[c+1] = d^L * a_start[c] + s[c].
__global__ void ema_phase2(const float* __restrict__ init,
                           const float* __restrict__ smooth) {
    const int tid = blockIdx.x * blockDim.x + threadIdx.x;
    if (tid >= B * F4) return;
    const int b  = tid / F4;
    const int f4 = tid % F4;

    const float w = load_w(smooth);
    const float d = 1.0f - w;
    float dl = d;
    #pragma unroll
    for (int i = 0; i < 7; ++i) dl *= dl;   // d^128 (L = 2^7), exact squarings

    float4 a = __ldg(reinterpret_cast<const float4*>(init) + (size_t)b * F4 + f4);
    #pragma unroll 4
    for (int c = 0; c < NC; ++c) {
        const size_t idx = ((size_t)b * NC + c) * F4 + f4;
        g_a0[idx] = a;
        const float4 s = g_s[idx];
        a.x = fmaf(dl, a.x, s.x);
        a.y = fmaf(dl, a.y, s.y);
        a.z = fmaf(dl, a.z, s.z);
        a.w = fmaf(dl, a.w, s.w);
    }
}

// Phase 3: rescan each chunk from its true start state, write output.
__global__ void __launch_bounds__(F4) ema_phase3(const float* __restrict__ x,
                                                 const float* __restrict__ smooth,
                                                 float* __restrict__ out) {
    const int c  = blockIdx.x;
    const int b  = blockIdx.y;
    const int f4 = threadIdx.x;
    const float w = load_w(smooth);
    const float d = 1.0f - w;

    const size_t base = (size_t)b * T * F4 + (size_t)c * L * F4 + f4;
    const float4* xp = reinterpret_cast<const float4*>(x) + base;
    float4*       op = reinterpret_cast<float4*>(out) + base;

    float4 a = g_a0[((size_t)b * NC + c) * F4 + f4];
    #pragma unroll 8
    for (int j = 0; j < L; ++j) {
        const float4 v = __ldg(xp + (size_t)j * F4);
        a.x = fmaf(d, a.x, w * v.x);
        a.y = fmaf(d, a.y, w * v.y);
        a.z = fmaf(d, a.z, w * v.z);
        a.w = fmaf(d, a.w, w * v.w);
        op[(size_t)j * F4] = a;
    }
}

extern "C" void kernel_launch(void* const* d_in, const int* in_sizes, int n_in,
                              void* d_out, int out_size) {
    const float* x      = (const float*)d_in[0];
    const float* init   = (const float*)d_in[1];
    const float* smooth = (const float*)d_in[2];
    float* out          = (float*)d_out;

    dim3 grid(NC, B);
    ema_phase1<<<grid, F4>>>(x, smooth);
    ema_phase2<<<(B * F4 + 255) / 256, 256>>>(init, smooth);
    ema_phase3<<<grid, F4>>>(x, smooth, out);
}